// round 4
// baseline (speedup 1.0000x reference)
#include <cuda_runtime.h>
#include <cooperative_groups.h>

namespace cg = cooperative_groups;

#define EPS 1e-8f
typedef unsigned long long ull;

// Shapes: b=4, m=8, n=128, d=64
__device__ float g_buf[4 * 8 * 128 * 128];
__device__ float g_rowpart[4 * 8 * 128];

__device__ __forceinline__ float warpReduceSum(float v) {
#pragma unroll
    for (int o = 16; o; o >>= 1) v += __shfl_xor_sync(0xffffffffu, v, o);
    return v;
}
__device__ __forceinline__ float warpReduceMax(float v) {
#pragma unroll
    for (int o = 16; o; o >>= 1) v = fmaxf(v, __shfl_xor_sync(0xffffffffu, v, o));
    return v;
}

__device__ __forceinline__ ull pk2(float x, float y) {
    ull r;
    asm("mov.b64 %0, {%1, %2};" : "=l"(r) : "f"(x), "f"(y));
    return r;
}
__device__ __forceinline__ float lo2(ull a) {
    float x;
    asm("{ .reg .b32 hi; mov.b64 {%0, hi}, %1; }" : "=f"(x) : "l"(a));
    return x;
}
__device__ __forceinline__ float hi2(ull a) {
    float x;
    asm("{ .reg .b32 lo; mov.b64 {lo, %0}, %1; }" : "=f"(x) : "l"(a));
    return x;
}
__device__ __forceinline__ ull fma2(ull a, ull b, ull c) {
    ull d;
    asm("fma.rn.f32x2 %0, %1, %2, %3;" : "=l"(d) : "l"(a), "l"(b), "l"(c));
    return d;
}
// acc2 += sign2 .* |gw2 + th2|
__device__ __forceinline__ void mac2(ull& acc, ull gw, ull th, unsigned sl, unsigned sh2) {
    asm("{\n\t"
        ".reg .b64 h2, t2;\n\t"
        ".reg .b32 lo, hi;\n\t"
        "add.rn.f32x2 h2, %1, %2;\n\t"
        "mov.b64 {lo, hi}, h2;\n\t"
        "lop3.b32 lo, lo, 0x7fffffff, %3, 0x6A;\n\t"
        "lop3.b32 hi, hi, 0x7fffffff, %4, 0x6A;\n\t"
        "mov.b64 t2, {lo, hi};\n\t"
        "add.rn.f32x2 %0, %0, t2;\n\t"
        "}"
        : "+l"(acc)
        : "l"(gw), "l"(th), "r"(sl), "r"(sh2));
}

// ---------------------------------------------------------------------------
// K1 k_fused: projections + scores + max-sub + exp + layer-0 row sums.
// grid (32, 4) = (f-quad, b), 512 threads.  t = tid>>2 (0..127), eq = tid&3
// owns e-range [eq*16, eq*16+16).  Thread computes its own T'[t] segment in
// regs; scores accumulated per (m,floc) over own e-range, reduced over eq via
// xor-1/2 shuffles.  All maxes / row sums are block-local.
// ---------------------------------------------------------------------------
__global__ void __launch_bounds__(512) k_fused(const float* __restrict__ cities,
                                               const float* __restrict__ groups,
                                               const float* __restrict__ W1,
                                               const float* __restrict__ b1,
                                               const float* __restrict__ W2,
                                               const float* __restrict__ b2) {
    const int b = blockIdx.y;
    const int blk = blockIdx.x;
    const int f0 = blk * 4;
    const int tid = threadIdx.x;
    const int w = tid >> 5, lane = tid & 31;
    const int t = tid >> 2, eq = tid & 3;

    __shared__ float s_Wt[64 * 64];    // Wt staged [k][e], 16KB
    __shared__ float s_Af[8][64];      // hg * |w|
    __shared__ float s_Ff[4][64];      // (hf + b1) * |w|
    __shared__ ull s_gw[8][4][32];     // packed A'+F', 8KB
    __shared__ unsigned s_sgnu[64];
    __shared__ float s_absw[64];
    __shared__ float s_wsgn[64];
    __shared__ float s_linp[8][2];
    __shared__ float s_linpF[4][2];
    __shared__ float s_linG[8];
    __shared__ float s_linF[4];
    __shared__ float s_mx[4][16];
    __shared__ float s_mx0[8][16];
    __shared__ float s_mxC[4];
    __shared__ float s_mx0C[8];
    __shared__ float s_rs[32][16];

    // ---- P0: W2-derived + stage Wt ----
    if (tid < 64) {
        float wv = W2[tid];
        s_absw[tid] = fabsf(wv);
        s_wsgn[tid] = wv;
        s_sgnu[tid] = __float_as_uint(wv) & 0x80000000u;
    }
    for (int i = tid; i < 4096; i += 512) s_Wt[i] = W1[8192 + i];  // rows 128..191
    __syncthreads();

    // ---- P1: hg (all 512 threads; m=tid>>6, e=tid&63) ----
    {
        int m = tid >> 6, e = tid & 63;
        const float* g = groups + (b * 8 + m) * 64;
        float acc = 0.f;
#pragma unroll
        for (int k = 0; k < 64; k++) acc += g[k] * W1[k * 64 + e];
        s_Af[m][e] = acc * s_absw[e];
        float lp = warpReduceSum(acc * s_wsgn[e]);
        if (lane == 0) s_linp[m][(e >> 5)] = lp;
    }
    // ---- P2: hf for 4 f's (threads 0..255) ----
    if (tid < 256) {
        int floc = tid >> 6, e = tid & 63;
        const float* c = cities + (b * 128 + f0 + floc) * 64;
        float acc = 0.f;
#pragma unroll
        for (int k = 0; k < 64; k++) acc += c[k] * W1[4096 + k * 64 + e];
        acc += b1[e];
        s_Ff[floc][e] = acc * s_absw[e];
        float lp = warpReduceSum(acc * s_wsgn[e]);
        if (lane == 0) s_linpF[floc][(e >> 5)] = lp;
    }
    __syncthreads();

    if (tid < 8) s_linG[tid] = s_linp[tid][0] + s_linp[tid][1];
    if (tid >= 8 && tid < 12) s_linF[tid - 8] = s_linpF[tid - 8][0] + s_linpF[tid - 8][1];

    // ---- P3: stage packed gw = A' + F' ----
    for (int i = tid; i < 1024; i += 512) {
        int m = i >> 7, rest = i & 127, floc = rest >> 5, e2 = rest & 31;
        float a0 = s_Af[m][2 * e2] + s_Ff[floc][2 * e2];
        float a1 = s_Af[m][2 * e2 + 1] + s_Ff[floc][2 * e2 + 1];
        s_gw[m][floc][e2] = pk2(a0, a1);
    }

    // ---- P4: T' for own (t, e-range): 16 e values packed in 8 ull ----
    ull T2[8];
#pragma unroll
    for (int p = 0; p < 8; p++) T2[p] = 0ull;
    {
        const float4* crow = (const float4*)(cities + (size_t)(b * 128 + t) * 64);
        const float* wtb = s_Wt + eq * 16;
#pragma unroll
        for (int kc = 0; kc < 16; kc++) {
            float4 cv = crow[kc];
            float cs[4] = {cv.x, cv.y, cv.z, cv.w};
#pragma unroll
            for (int j = 0; j < 4; j++) {
                ull c2 = pk2(cs[j], cs[j]);
                const ull* wrow = (const ull*)(wtb + (kc * 4 + j) * 64);
#pragma unroll
                for (int p = 0; p < 8; p++) T2[p] = fma2(c2, wrow[p], T2[p]);
            }
        }
    }
    float linT;
    {
        float linTp = 0.f;
#pragma unroll
        for (int p = 0; p < 8; p++) {
            float t0 = lo2(T2[p]), t1 = hi2(T2[p]);
            int e = eq * 16 + 2 * p;
            linTp += t0 * s_wsgn[e] + t1 * s_wsgn[e + 1];
            T2[p] = pk2(t0 * s_absw[e], t1 * s_absw[e + 1]);
        }
#pragma unroll
        for (int o = 1; o <= 2; o <<= 1) linTp += __shfl_xor_sync(0xffffffffu, linTp, o);
        linT = linTp;
    }
    __syncthreads();  // s_gw ready

    // ---- P5: scores (partial over own e-range) ----
    float v[8][4];
#pragma unroll
    for (int floc = 0; floc < 4; floc++) {
        ull acc[8];
#pragma unroll
        for (int m = 0; m < 8; m++) acc[m] = 0ull;
#pragma unroll
        for (int p = 0; p < 8; p++) {
            int e2 = eq * 8 + p;
            unsigned sl = s_sgnu[2 * e2], sh2v = s_sgnu[2 * e2 + 1];
            ull th = T2[p];
#pragma unroll
            for (int m = 0; m < 8; m++) mac2(acc[m], s_gw[m][floc][e2], th, sl, sh2v);
        }
#pragma unroll
        for (int m = 0; m < 8; m++) v[m][floc] = lo2(acc[m]) + hi2(acc[m]);
    }

    // ---- P6: reduce over eq (xor 1,2) + finalize scores ----
#pragma unroll
    for (int m = 0; m < 8; m++)
#pragma unroll
        for (int floc = 0; floc < 4; floc++) {
#pragma unroll
            for (int o = 1; o <= 2; o <<= 1)
                v[m][floc] += __shfl_xor_sync(0xffffffffu, v[m][floc], o);
        }
    {
        float b2v = b2[0];
#pragma unroll
        for (int m = 0; m < 8; m++) {
            float lg = s_linG[m];
#pragma unroll
            for (int floc = 0; floc < 4; floc++)
                v[m][floc] = 0.5f * (lg + s_linF[floc] + linT + v[m][floc]) + b2v;
        }
    }

    // ---- P7: maxes (block-local over m,t) ----
#pragma unroll
    for (int floc = 0; floc < 4; floc++) {
        float lm = v[0][floc];
#pragma unroll
        for (int m = 1; m < 8; m++) lm = fmaxf(lm, v[m][floc]);
        lm = warpReduceMax(lm);
        if (lane == 0) s_mx[floc][w] = lm;
    }
    if (blk == 0) {
#pragma unroll
        for (int m = 0; m < 8; m++) {
            float mm = warpReduceMax(v[m][0]);
            if (lane == 0) s_mx0[m][w] = mm;
        }
    }
    __syncthreads();
    if (tid < 4) {
        float mx = s_mx[tid][0];
#pragma unroll
        for (int ww = 1; ww < 16; ww++) mx = fmaxf(mx, s_mx[tid][ww]);
        s_mxC[tid] = mx;
    }
    if (blk == 0 && tid >= 4 && tid < 12) {
        int m = tid - 4;
        float mx = s_mx0[m][0];
#pragma unroll
        for (int ww = 1; ww < 16; ww++) mx = fmaxf(mx, s_mx0[m][ww]);
        s_mx0C[m] = mx;
    }
    __syncthreads();

    // ---- P8: exp + write g_buf + layer-0 row sums ----
#pragma unroll
    for (int mi = 0; mi < 2; mi++) {
        int m = eq * 2 + mi;
#pragma unroll
        for (int floc = 0; floc < 4; floc++) {
            float mxx = (blk == 0 && floc == 0) ? s_mx0C[m] : s_mxC[floc];
            float ev = expf(v[m][floc] - mxx);
            g_buf[(((size_t)(b * 8 + m)) * 128 + f0 + floc) * 128 + t] = ev;
            float r = fmaxf(ev, EPS);
#pragma unroll
            for (int o = 4; o <= 16; o <<= 1) r += __shfl_xor_sync(0xffffffffu, r, o);
            if (lane == eq) s_rs[m * 4 + floc][w] = r;
        }
    }
    __syncthreads();
    if (tid < 32) {
        int m = tid >> 2, fl = tid & 3;
        float s = 0.f;
#pragma unroll
        for (int ww = 0; ww < 16; ww++) s += s_rs[tid][ww];
        g_rowpart[(b * 8 + m) * 128 + f0 + fl] = s;
    }
}

// ---------------------------------------------------------------------------
// K2 k_soft: all 10 layers (unchanged from round 3 — passed).
// ---------------------------------------------------------------------------
__global__ void __cluster_dims__(8, 1, 1) __launch_bounds__(512) k_soft(float* __restrict__ out) {
    cg::cluster_group cl = cg::this_cluster();
    const int rk = (int)cl.block_rank();
    const int b = blockIdx.x >> 3;
    const int tid = threadIdx.x;
    const int x = tid & 127;
    const int jq = tid >> 7;
    const int w = tid >> 5;
    const int xw = w & 3;
    const int lane = tid & 31;
    const int yb = rk * 16;
    const bool x0 = (x == 0);

    __shared__ float s_xs[2][128];
    __shared__ float s_x0[2][8];
    __shared__ float s_dinv[128];
    __shared__ float s_d0inv[8];
    __shared__ float s_cden[16];
    __shared__ float s_c0inv[8];
    __shared__ float s_wp[4][4][4];
    __shared__ float s_w0[4][8];
    __shared__ float s_rp[4][128];
    __shared__ float s_rp0[4][8];

    float v[8][4];
#pragma unroll
    for (int m = 0; m < 8; m++) {
        const float4* p =
            (const float4*)(g_buf + ((size_t)((b * 8 + m) * 128 + x)) * 128 + yb + jq * 4);
        float4 t4 = *p;
        v[m][0] = t4.x; v[m][1] = t4.y; v[m][2] = t4.z; v[m][3] = t4.w;
    }

    if (tid < 128) {
        if (tid == 0) {
            s_dinv[0] = 0.f;
        } else {
            float d = 0.f;
#pragma unroll
            for (int m = 0; m < 8; m++) d += g_rowpart[(b * 8 + m) * 128 + tid];
            s_dinv[tid] = 1.0f / d;
        }
    }
    if (tid < 8) s_d0inv[tid] = 1.0f / g_rowpart[(b * 8 + tid) * 128];
    __syncthreads();

#pragma unroll 1
    for (int half = 0; half < 5; half++) {
        {
            float rinv = s_dinv[x];
#pragma unroll
            for (int m = 0; m < 8; m++) {
                float dm = x0 ? s_d0inv[m] : rinv;
#pragma unroll
                for (int jj = 0; jj < 4; jj++) v[m][jj] = fmaxf(v[m][jj], EPS) * dm;
            }
        }
        {
            float cp[4];
#pragma unroll
            for (int jj = 0; jj < 4; jj++) {
                float s = 0.f;
#pragma unroll
                for (int m = 0; m < 8; m++) s += fmaxf(v[m][jj], EPS);
                cp[jj] = warpReduceSum(s);
            }
            if (lane == 0) {
#pragma unroll
                for (int jj = 0; jj < 4; jj++) s_wp[jq][xw][jj] = cp[jj];
            }
            if (rk == 0 && jq == 0) {
#pragma unroll
                for (int m = 0; m < 8; m++) {
                    float s = warpReduceSum(fmaxf(v[m][0], EPS));
                    if (lane == 0) s_w0[xw][m] = s;
                }
            }
            __syncthreads();
            if (tid < 16) {
                int jqq = tid >> 2, jjj = tid & 3;
                s_cden[tid] = 1.0f / (s_wp[jqq][0][jjj] + s_wp[jqq][1][jjj] +
                                      s_wp[jqq][2][jjj] + s_wp[jqq][3][jjj]);
            }
            if (rk == 0 && tid < 8)
                s_c0inv[tid] = 1.0f / (s_w0[0][tid] + s_w0[1][tid] + s_w0[2][tid] + s_w0[3][tid]);
            __syncthreads();
        }

        float rj[4];
#pragma unroll
        for (int jj = 0; jj < 4; jj++) rj[jj] = s_cden[jq * 4 + jj];
        bool y0 = (rk == 0 && jq == 0);

        if (half == 4) {
#pragma unroll
            for (int m = 0; m < 8; m++) {
                float4 o;
                o.x = fmaxf(v[m][0], EPS) * (y0 ? s_c0inv[m] : rj[0]);
                o.y = fmaxf(v[m][1], EPS) * rj[1];
                o.z = fmaxf(v[m][2], EPS) * rj[2];
                o.w = fmaxf(v[m][3], EPS) * rj[3];
                *(float4*)(out + ((size_t)((b * 8 + m) * 128 + x)) * 128 + yb + jq * 4) = o;
            }
            break;
        }

#pragma unroll
        for (int m = 0; m < 8; m++) {
            v[m][0] = fmaxf(v[m][0], EPS) * (y0 ? s_c0inv[m] : rj[0]);
#pragma unroll
            for (int jj = 1; jj < 4; jj++) v[m][jj] = fmaxf(v[m][jj], EPS) * rj[jj];
        }

        int p = half & 1;
        {
            float rp = 0.f;
#pragma unroll
            for (int m = 0; m < 8; m++) {
#pragma unroll
                for (int jj = 0; jj < 4; jj++) rp += fmaxf(v[m][jj], EPS);
            }
            s_rp[jq][x] = rp;
            if (x0) {
#pragma unroll
                for (int m = 0; m < 8; m++) {
                    float s = fmaxf(v[m][0], EPS) + fmaxf(v[m][1], EPS) +
                              fmaxf(v[m][2], EPS) + fmaxf(v[m][3], EPS);
                    s_rp0[jq][m] = s;
                }
            }
            __syncthreads();
            if (tid < 128)
                s_xs[p][tid] = s_rp[0][tid] + s_rp[1][tid] + s_rp[2][tid] + s_rp[3][tid];
            if (tid < 8)
                s_x0[p][tid] = s_rp0[0][tid] + s_rp0[1][tid] + s_rp0[2][tid] + s_rp0[3][tid];
        }
        cl.sync();

        if (tid < 128) {
            if (tid == 0) {
                s_dinv[0] = 0.f;
            } else {
                float d = 0.f;
#pragma unroll
                for (int r = 0; r < 8; r++) {
                    const float* pp = cl.map_shared_rank((const float*)&s_xs[p][0], r);
                    d += pp[tid];
                }
                s_dinv[tid] = 1.0f / d;
            }
        }
        if (tid < 8) {
            float d = 0.f;
#pragma unroll
            for (int r = 0; r < 8; r++) {
                const float* pp = cl.map_shared_rank((const float*)&s_x0[p][0], r);
                d += pp[tid];
            }
            s_d0inv[tid] = 1.0f / d;
        }
        __syncthreads();
    }

    cl.sync();
}

// ---------------------------------------------------------------------------
// Launch: 2 kernels.
// ---------------------------------------------------------------------------
extern "C" void kernel_launch(void* const* d_in, const int* in_sizes, int n_in,
                              void* d_out, int out_size) {
    const float* cities = (const float*)d_in[0];
    const float* groups = (const float*)d_in[1];
    const float* W1 = (const float*)d_in[2];
    const float* b1 = (const float*)d_in[3];
    const float* W2 = (const float*)d_in[4];
    const float* b2 = (const float*)d_in[5];
    float* out = (float*)d_out;

    k_fused<<<dim3(32, 4), 512>>>(cities, groups, W1, b1, W2, b2);
    k_soft<<<32, 512>>>(out);
}

// round 5
// speedup vs baseline: 1.7742x; 1.7742x over previous
#include <cuda_runtime.h>
#include <cooperative_groups.h>

namespace cg = cooperative_groups;

#define EPS 1e-8f
typedef unsigned long long ull;

// Shapes: b=4, m=8, n=128, d=64
__device__ float g_hgw[4 * 8 * 64];     // hg * |w|
__device__ float g_hfw[4 * 128 * 64];   // (hf + b1) * |w|
__device__ float g_htw[4 * 128 * 64];   // ht * |w|
__device__ float g_linG[4 * 8];         // sum_e hg*w
__device__ float g_linF[4 * 128];       // sum_e (hf+b1)*w
__device__ float g_linT[4 * 128];       // sum_e ht*w
__device__ unsigned g_sgnu[64];         // sign mask of W2 per e
__device__ float g_buf[4 * 8 * 128 * 128];
__device__ float g_rowpart[4 * 8 * 128];

__device__ __forceinline__ float warpReduceSum(float v) {
#pragma unroll
    for (int o = 16; o; o >>= 1) v += __shfl_xor_sync(0xffffffffu, v, o);
    return v;
}
__device__ __forceinline__ float warpReduceMax(float v) {
#pragma unroll
    for (int o = 16; o; o >>= 1) v = fmaxf(v, __shfl_xor_sync(0xffffffffu, v, o));
    return v;
}

// acc2 += sign2 .* |gw2 + th2|
__device__ __forceinline__ void mac2(ull& acc, ull gw, ull th, unsigned sl, unsigned sh2) {
    asm("{\n\t"
        ".reg .b64 h2, t2;\n\t"
        ".reg .b32 lo, hi;\n\t"
        "add.rn.f32x2 h2, %1, %2;\n\t"
        "mov.b64 {lo, hi}, h2;\n\t"
        "lop3.b32 lo, lo, 0x7fffffff, %3, 0x6A;\n\t"
        "lop3.b32 hi, hi, 0x7fffffff, %4, 0x6A;\n\t"
        "mov.b64 t2, {lo, hi};\n\t"
        "add.rn.f32x2 %0, %0, t2;\n\t"
        "}"
        : "+l"(acc)
        : "l"(gw), "l"(th), "r"(sl), "r"(sh2));
}

// ---------------------------------------------------------------------------
// K1 k_proj (R2-verbatim, known 7.3us): grid (264,4), block 64.
// ---------------------------------------------------------------------------
__global__ void k_proj(const float* __restrict__ cities, const float* __restrict__ groups,
                       const float* __restrict__ W1, const float* __restrict__ b1,
                       const float* __restrict__ W2) {
    int b = blockIdx.y;
    int r = blockIdx.x;
    int e = threadIdx.x;
    __shared__ float xv[64];
    __shared__ float sred2[2];

    const float* x;
    float* outw;
    float* lin;
    int woff;
    float badd = 0.f;
    if (r < 8) {
        x = groups + (b * 8 + r) * 64;
        outw = g_hgw + (b * 8 + r) * 64;
        lin = g_linG + b * 8 + r;
        woff = 0;
    } else if (r < 136) {
        int f = r - 8;
        x = cities + (b * 128 + f) * 64;
        outw = g_hfw + (b * 128 + f) * 64;
        lin = g_linF + b * 128 + f;
        woff = 64;
        badd = b1[e];
    } else {
        int t = r - 136;
        x = cities + (b * 128 + t) * 64;
        outw = g_htw + (b * 128 + t) * 64;
        lin = g_linT + b * 128 + t;
        woff = 128;
    }
    xv[e] = x[e];
    if (r == 0 && b == 0) g_sgnu[e] = (W2[e] < 0.f) ? 0x80000000u : 0u;
    __syncthreads();

    float acc = 0.f;
#pragma unroll
    for (int k = 0; k < 64; k++) acc += xv[k] * W1[(woff + k) * 64 + e];
    float h = acc + badd;
    float w = W2[e];
    outw[e] = h * fabsf(w);

    float p = warpReduceSum(h * w);
    if ((e & 31) == 0) sred2[e >> 5] = p;
    __syncthreads();
    if (e == 0) *lin = sred2[0] + sred2[1];
}

// ---------------------------------------------------------------------------
// K2 k_out (R2-verbatim): grid (128,4) x 128.
// ---------------------------------------------------------------------------
__global__ void __launch_bounds__(128) k_out(const float* __restrict__ b2) {
    int b = blockIdx.y, f = blockIdx.x, t = threadIdx.x;
    int w = t >> 5, lane = t & 31;
    __shared__ ull sh_gw[8 * 32];
    __shared__ unsigned sh_sgu[64];
    __shared__ float sh_linG[8];
    __shared__ float s_red[8][4];
    __shared__ float s_bc[8];
    __shared__ float s_m4[4];

    for (int idx = t; idx < 256; idx += 128) {
        int m = idx >> 5, ee2 = idx & 31;
        int e = 2 * ee2;
        float a0 = g_hgw[(b * 8 + m) * 64 + e] + g_hfw[(b * 128 + f) * 64 + e];
        float a1 = g_hgw[(b * 8 + m) * 64 + e + 1] + g_hfw[(b * 128 + f) * 64 + e + 1];
        sh_gw[m * 32 + ee2] = (ull)__float_as_uint(a0) | ((ull)__float_as_uint(a1) << 32);
    }
    if (t < 64) sh_sgu[t] = g_sgnu[t];
    if (t < 8) sh_linG[t] = g_linG[b * 8 + t];
    __syncthreads();

    union {
        float4 f4[16];
        ull u[32];
    } tw;
    const float4* src = (const float4*)(g_htw + (b * 128 + t) * 64);
#pragma unroll
    for (int i = 0; i < 16; i++) tw.f4[i] = src[i];

    ull accs[8];
#pragma unroll
    for (int m = 0; m < 8; m++) accs[m] = 0ull;
#pragma unroll
    for (int ee2 = 0; ee2 < 32; ee2++) {
        unsigned sl = sh_sgu[2 * ee2], sh2 = sh_sgu[2 * ee2 + 1];
        ull th = tw.u[ee2];
#pragma unroll
        for (int m = 0; m < 8; m++) mac2(accs[m], sh_gw[m * 32 + ee2], th, sl, sh2);
    }

    float linFT = g_linF[b * 128 + f] + g_linT[b * 128 + t];
    float b2v = b2[0];
    float vals[8];
#pragma unroll
    for (int m = 0; m < 8; m++) {
        float nl = __uint_as_float((unsigned)(accs[m] & 0xffffffffull)) +
                   __uint_as_float((unsigned)(accs[m] >> 32));
        vals[m] = 0.5f * (sh_linG[m] + linFT + nl) + b2v;
    }

    if (f == 0) {
#pragma unroll
        for (int m = 0; m < 8; m++) {
            float mm = warpReduceMax(vals[m]);
            if (lane == 0) s_red[m][w] = mm;
        }
        __syncthreads();
        if (t < 8) s_bc[t] = fmaxf(fmaxf(s_red[t][0], s_red[t][1]), fmaxf(s_red[t][2], s_red[t][3]));
        __syncthreads();
#pragma unroll
        for (int m = 0; m < 8; m++) {
            float ev = expf(vals[m] - s_bc[m]);
            g_buf[((b * 8 + m) * 128 + 0) * 128 + t] = ev;
            float s = warpReduceSum(fmaxf(ev, EPS));
            if (lane == 0) s_red[m][w] = s;
        }
        __syncthreads();
        if (t < 8)
            g_rowpart[(b * 8 + t) * 128 + 0] = s_red[t][0] + s_red[t][1] + s_red[t][2] + s_red[t][3];
    } else {
        float lm = vals[0];
#pragma unroll
        for (int m = 1; m < 8; m++) lm = fmaxf(lm, vals[m]);
        lm = warpReduceMax(lm);
        if (lane == 0) s_m4[w] = lm;
        __syncthreads();
        float mx = fmaxf(fmaxf(s_m4[0], s_m4[1]), fmaxf(s_m4[2], s_m4[3]));
#pragma unroll
        for (int m = 0; m < 8; m++) {
            float ev = expf(vals[m] - mx);
            g_buf[((b * 8 + m) * 128 + f) * 128 + t] = ev;
            float s = warpReduceSum(fmaxf(ev, EPS));
            if (lane == 0) s_red[m][w] = s;
        }
        __syncthreads();
        if (t < 8)
            g_rowpart[(b * 8 + t) * 128 + f] = s_red[t][0] + s_red[t][1] + s_red[t][2] + s_red[t][3];
    }
}

// ---------------------------------------------------------------------------
// K3 k_soft v3: all 10 layers. Grid 32 = 4 clusters of 8 (cluster = batch).
// 1024 threads: tid = x*8 + jq  (x = tid>>3 in [0,128), jq = tid&7).
// Thread owns v[m][j] = P[b,m,x, y = rk*16 + jq*2 + j], m=0..7, j=0..1.
// Warp = 4 consecutive x * all 8 jq -> even-layer per-x sums are IN-WARP
// (xor 1,2,4 over jq); odd-layer per-y sums use xor 8,16 (over 4 x) + one
// smem stage over 32 warps. 3 __syncthreads + 1 cluster.sync per layer pair.
// ---------------------------------------------------------------------------
__global__ void __cluster_dims__(8, 1, 1) __launch_bounds__(1024, 1)
k_soft(float* __restrict__ out) {
    cg::cluster_group cl = cg::this_cluster();
    const int rk = (int)cl.block_rank();
    const int b = blockIdx.x >> 3;
    const int tid = threadIdx.x;
    const int x = tid >> 3;
    const int jq = tid & 7;
    const int w = tid >> 5;
    const int lane = tid & 31;
    const int yb = rk * 16;
    const bool x0 = (x == 0);
    const bool y0 = (rk == 0 && jq == 0);  // this thread's j==0 element is y==0

    __shared__ float s_dinv[128];   // 1/den(x) for even layers
    __shared__ float s_d0inv[8];    // 1/den(x==0, m)
    __shared__ float s_cdinv[16];   // 1/den(local y) for odd layers
    __shared__ float s_c0inv[8];    // 1/den(y==0, m)  (rank 0 only)
    __shared__ float s_wpp[32][16]; // [warp][jq*2+j] odd-den partials
    __shared__ float s_y0p[32][8];  // [warp][m] y==0 partials (rank 0)
    __shared__ float s_xs[2][128];  // exchanged per-x local sums
    __shared__ float s_x0[2][8];    // exchanged per-m x==0 local sums

    // ---- load slab (warp reads 4 rows x 64B contiguous per m) ----
    float v[8][2];
#pragma unroll
    for (int m = 0; m < 8; m++) {
        const float2* p =
            (const float2*)(g_buf + ((size_t)((b * 8 + m) * 128 + x)) * 128 + yb + jq * 2);
        float2 t2 = *p;
        v[m][0] = t2.x;
        v[m][1] = t2.y;
    }

    // ---- layer-0 even dens from g_rowpart ----
    if (tid < 128) {
        float d = 0.f;
#pragma unroll
        for (int m = 0; m < 8; m++) d += g_rowpart[(b * 8 + m) * 128 + tid];
        s_dinv[tid] = 1.0f / d;
    } else if (tid < 136) {
        s_d0inv[tid - 128] = 1.0f / g_rowpart[(b * 8 + (tid - 128)) * 128];
    }
    __syncthreads();

#pragma unroll 1
    for (int half = 0; half < 5; half++) {
        // ===== EVEN layer scale + odd-den partials =====
        float sj0 = 0.f, sj1 = 0.f;
        {
            float rinv = s_dinv[x];
#pragma unroll
            for (int m = 0; m < 8; m++) {
                float dm = x0 ? s_d0inv[m] : rinv;
                float a0 = fmaxf(v[m][0], EPS) * dm;
                float a1 = fmaxf(v[m][1], EPS) * dm;
                v[m][0] = a0;
                v[m][1] = a1;
                sj0 += fmaxf(a0, EPS);
                sj1 += fmaxf(a1, EPS);
            }
        }
        // reduce over the 4 x's in this warp (xor 8, 16 preserve jq)
        sj0 += __shfl_xor_sync(0xffffffffu, sj0, 8);
        sj0 += __shfl_xor_sync(0xffffffffu, sj0, 16);
        sj1 += __shfl_xor_sync(0xffffffffu, sj1, 8);
        sj1 += __shfl_xor_sync(0xffffffffu, sj1, 16);
        if ((lane >> 3) == 0) {  // xloc==0 lanes: lane == jq
            s_wpp[w][jq * 2 + 0] = sj0;
            s_wpp[w][jq * 2 + 1] = sj1;
        }
        if (rk == 0) {  // y==0 per-m partials (only jq==0 lanes hold y==0 data)
#pragma unroll
            for (int m = 0; m < 8; m++) {
                float t = fmaxf(v[m][0], EPS);
                t += __shfl_xor_sync(0xffffffffu, t, 8);
                t += __shfl_xor_sync(0xffffffffu, t, 16);
                if (lane == 0) s_y0p[w][m] = t;
            }
        }
        __syncthreads();  // bar1
        if (tid < 16) {
            float d = 0.f;
#pragma unroll
            for (int ww = 0; ww < 32; ww++) d += s_wpp[ww][tid];
            s_cdinv[tid] = 1.0f / d;
        } else if (tid < 24 && rk == 0) {
            int m = tid - 16;
            float d = 0.f;
#pragma unroll
            for (int ww = 0; ww < 32; ww++) d += s_y0p[ww][m];
            s_c0inv[m] = 1.0f / d;
        }
        __syncthreads();  // bar2

        // ===== ODD layer scale =====
        float rj0 = s_cdinv[jq * 2], rj1 = s_cdinv[jq * 2 + 1];
        if (half == 4) {
#pragma unroll
            for (int m = 0; m < 8; m++) {
                float2 o;
                o.x = fmaxf(v[m][0], EPS) * (y0 ? s_c0inv[m] : rj0);
                o.y = fmaxf(v[m][1], EPS) * rj1;
                *(float2*)(out + ((size_t)((b * 8 + m) * 128 + x)) * 128 + yb + jq * 2) = o;
            }
            break;
        }
        float rp = 0.f;
#pragma unroll
        for (int m = 0; m < 8; m++) {
            float a0 = fmaxf(v[m][0], EPS) * (y0 ? s_c0inv[m] : rj0);
            float a1 = fmaxf(v[m][1], EPS) * rj1;
            v[m][0] = a0;
            v[m][1] = a1;
            rp += fmaxf(a0, EPS) + fmaxf(a1, EPS);
        }
        // even-den per-x local sum: reduce over jq IN-WARP (xor 1,2,4)
        rp += __shfl_xor_sync(0xffffffffu, rp, 1);
        rp += __shfl_xor_sync(0xffffffffu, rp, 2);
        rp += __shfl_xor_sync(0xffffffffu, rp, 4);
        int p = half & 1;
        if ((lane & 7) == 0) s_xs[p][x] = rp;
        // x==0 per-m local sums: warp 0, lanes 0..7 (x==0, jq=lane)
        if (w == 0) {
#pragma unroll
            for (int m = 0; m < 8; m++) {
                float t = fmaxf(v[m][0], EPS) + fmaxf(v[m][1], EPS);
                t += __shfl_xor_sync(0xffffffffu, t, 1);
                t += __shfl_xor_sync(0xffffffffu, t, 2);
                t += __shfl_xor_sync(0xffffffffu, t, 4);
                if (lane == 0) s_x0[p][m] = t;
            }
        }
        cl.sync();  // full block sync + cluster visibility

        // ---- gather peers' sums -> next even dens ----
        if (tid < 128) {
            float d = 0.f;
#pragma unroll
            for (int r = 0; r < 8; r++) {
                const float* pp = cl.map_shared_rank((const float*)&s_xs[p][0], r);
                d += pp[tid];
            }
            s_dinv[tid] = 1.0f / d;
        } else if (tid < 136) {
            int m = tid - 128;
            float d = 0.f;
#pragma unroll
            for (int r = 0; r < 8; r++) {
                const float* pp = cl.map_shared_rank((const float*)&s_x0[p][0], r);
                d += pp[m];
            }
            s_d0inv[m] = 1.0f / d;
        }
        __syncthreads();  // bar3
    }

    cl.sync();  // keep SMEM alive until all peers finished DSMEM reads
}

// ---------------------------------------------------------------------------
// Launch: 3 kernels.
// ---------------------------------------------------------------------------
extern "C" void kernel_launch(void* const* d_in, const int* in_sizes, int n_in,
                              void* d_out, int out_size) {
    const float* cities = (const float*)d_in[0];
    const float* groups = (const float*)d_in[1];
    const float* W1 = (const float*)d_in[2];
    const float* b1 = (const float*)d_in[3];
    const float* W2 = (const float*)d_in[4];
    const float* b2 = (const float*)d_in[5];
    float* out = (float*)d_out;

    k_proj<<<dim3(264, 4), 64>>>(cities, groups, W1, b1, W2);
    k_out<<<dim3(128, 4), 128>>>(b2);
    k_soft<<<32, 1024>>>(out);
}